// round 16
// baseline (speedup 1.0000x reference)
#include <cuda_runtime.h>
#include <math.h>
#include <stdint.h>
#include <mma.h>
using namespace nvcuda;

// Problem constants
#define BS 4096
#define NF 128
#define HF 256
#define HH 512          // 2*HF
#define NBLK 1024       // n = BS/M
#define NCLS 4

// ---------------- scratch ----------------------------------------------------
__device__ float    g_Y[BS * NF];                 // row-normalized features
__device__ unsigned g_Dbits[4 * NBLK * 32];       // diag block indicators (A)
__device__ unsigned g_Ebits[3 * NBLK * 32];       // B03,B13,B23 indicators
__device__ unsigned g_ETbits[3 * NBLK * 32];      // their bit-transposes
__device__ unsigned g_maskbits[BS * 128];         // mask rows, bit packed
__device__ unsigned g_maskTbits[BS * 128];        // mask^T rows, bit packed
__device__ float    g_a1[BS], g_s1[BS], g_a2[BS], g_s2[BS];
__device__ float    g_Z1[BS * HH];                // scratch
__device__ float    g_Z2[BS * HH];
__device__ float    g_h[BS * HH];                 // concat gin outputs
__device__ float    g_s1col[HH], g_c1[HH];        // BN1 scale / offset per col
__device__ float    g_s2col[HH], g_c2[HH];        // BN2 scale / offset per col
__device__ float    g_R1[HF], g_R2[HF];           // c1 @ W2 rank-1 bias rows

__device__ __forceinline__ float to_tf32(float x) {
    float r;
    asm("cvt.rna.tf32.f32 %0, %1;" : "=f"(r) : "f"(x));
    return r;
}

// ---------------- 1. row-normalize features ---------------------------------
__global__ void k_rownorm(const float* __restrict__ F) {
    int u    = blockIdx.x * 8 + (threadIdx.x >> 5);
    int lane = threadIdx.x & 31;
    float4 v = *(const float4*)(F + (size_t)u * NF + lane * 4);
    float s = v.x + v.y + v.z + v.w;
    #pragma unroll
    for (int o = 16; o; o >>= 1) s += __shfl_xor_sync(0xffffffffu, s, o);
    float m = s * (1.0f / NF);
    v.x -= m; v.y -= m; v.z -= m; v.w -= m;
    float ss = v.x*v.x + v.y*v.y + v.z*v.z + v.w*v.w;
    #pragma unroll
    for (int o = 16; o; o >>= 1) ss += __shfl_xor_sync(0xffffffffu, ss, o);
    float inv = 1.0f / sqrtf(ss);
    v.x *= inv; v.y *= inv; v.z *= inv; v.w *= inv;
    *(float4*)(g_Y + (size_t)u * NF + lane * 4) = v;
}

// ---------------- 2. correlation block indicators (128x64 tiles, 8x4/thr) ---
__global__ void k_corr_ind(const float* __restrict__ sparse) {
    const int t_bi[7]  = {0, 1, 2, 3, 0, 1, 2};
    const int t_bj[7]  = {0, 1, 2, 3, 3, 3, 3};
    const int t_cnt[7] = {1, 5, 8, 10, 4, 7, 9};
    int z  = blockIdx.z;
    int by = blockIdx.y;          // 0..7  (128-row tiles)
    int bx = blockIdx.x;          // 0..15 (64-col tiles)
    bool diag = (z < 4);
    if (diag && bx < 2 * by) return;          // fully below diagonal
    int bi = t_bi[z], bj = t_bj[z];
    float thr = 1.0f / (1.0f + expf(-sparse[t_cnt[z]]));
    unsigned* outb  = diag ? (g_Dbits + (size_t)z * NBLK * 32)
                           : (g_Ebits + (size_t)(z - 4) * NBLK * 32);
    unsigned* outbT = diag ? outb
                           : (g_ETbits + (size_t)(z - 4) * NBLK * 32);

    __shared__ __align__(16) float Ut[32][136];   // [k_local][row 0..127]
    __shared__ __align__(16) float Vt[32][72];    // [k_local][col 0..63]
    __shared__ unsigned sbits[128][2];
    __shared__ unsigned sbitsT[64][4];

    int t  = threadIdx.x;
    int tx = t & 15, ty = t >> 4;
    int u0 = bi * NBLK + by * 128;
    int v0 = bj * NBLK + bx * 64;

    sbits[t >> 1][t & 1]  = 0u;
    sbitsT[t >> 2][t & 3] = 0u;

    float acc[8][4] = {};
    int lrA = t >> 1, lqA = t & 1;   // A load: row, 16-k half
    int lrB = t >> 2, lqB = t & 3;   // B load: row, 8-k quarter
    #pragma unroll
    for (int pass = 0; pass < 4; pass++) {
        int k0 = pass * 32;
        if (pass) __syncthreads();
        #pragma unroll
        for (int m = 0; m < 4; m++) {
            int c = lqA * 16 + m * 4;
            float4 a = *(const float4*)(g_Y + (size_t)(u0 + lrA) * NF + k0 + c);
            Ut[c + 0][lrA] = a.x; Ut[c + 1][lrA] = a.y;
            Ut[c + 2][lrA] = a.z; Ut[c + 3][lrA] = a.w;
        }
        #pragma unroll
        for (int m = 0; m < 2; m++) {
            int c = lqB * 8 + m * 4;
            float4 b = *(const float4*)(g_Y + (size_t)(v0 + lrB) * NF + k0 + c);
            Vt[c + 0][lrB] = b.x; Vt[c + 1][lrB] = b.y;
            Vt[c + 2][lrB] = b.z; Vt[c + 3][lrB] = b.w;
        }
        __syncthreads();
        #pragma unroll 8
        for (int k = 0; k < 32; k++) {
            float4 a0 = *(const float4*)&Ut[k][ty * 8];
            float4 a1 = *(const float4*)&Ut[k][ty * 8 + 4];
            float4 b  = *(const float4*)&Vt[k][tx * 4];
            acc[0][0]+=a0.x*b.x; acc[0][1]+=a0.x*b.y; acc[0][2]+=a0.x*b.z; acc[0][3]+=a0.x*b.w;
            acc[1][0]+=a0.y*b.x; acc[1][1]+=a0.y*b.y; acc[1][2]+=a0.y*b.z; acc[1][3]+=a0.y*b.w;
            acc[2][0]+=a0.z*b.x; acc[2][1]+=a0.z*b.y; acc[2][2]+=a0.z*b.z; acc[2][3]+=a0.z*b.w;
            acc[3][0]+=a0.w*b.x; acc[3][1]+=a0.w*b.y; acc[3][2]+=a0.w*b.z; acc[3][3]+=a0.w*b.w;
            acc[4][0]+=a1.x*b.x; acc[4][1]+=a1.x*b.y; acc[4][2]+=a1.x*b.z; acc[4][3]+=a1.x*b.w;
            acc[5][0]+=a1.y*b.x; acc[5][1]+=a1.y*b.y; acc[5][2]+=a1.y*b.z; acc[5][3]+=a1.y*b.w;
            acc[6][0]+=a1.z*b.x; acc[6][1]+=a1.z*b.y; acc[6][2]+=a1.z*b.z; acc[6][3]+=a1.z*b.w;
            acc[7][0]+=a1.w*b.x; acc[7][1]+=a1.w*b.y; acc[7][2]+=a1.w*b.z; acc[7][3]+=a1.w*b.w;
        }
    }
    // threshold -> flags
    unsigned fl[8][4];
    #pragma unroll
    for (int i = 0; i < 8; i++) {
        int gu = u0 + ty * 8 + i;
        #pragma unroll
        for (int j = 0; j < 4; j++) {
            int gv = v0 + tx * 4 + j;
            float g  = fminf(fmaxf(acc[i][j], -1.0f), 1.0f);
            float aw = fabsf(g) - ((gu == gv) ? 1.0f : 0.0f);
            fl[i][j] = ((aw - thr) > 0.0f) ? 1u : 0u;
        }
    }
    {
        int wsel = tx >> 3, shift = (tx & 7) * 4;
        #pragma unroll
        for (int i = 0; i < 8; i++) {
            unsigned nib = fl[i][0] | (fl[i][1] << 1) | (fl[i][2] << 2) | (fl[i][3] << 3);
            if (nib) atomicOr(&sbits[ty * 8 + i][wsel], nib << shift);
        }
    }
    {
        int wsel = ty >> 2, shift = (ty & 3) * 8;
        #pragma unroll
        for (int j = 0; j < 4; j++) {
            unsigned byte = fl[0][j] | (fl[1][j] << 1) | (fl[2][j] << 2) | (fl[3][j] << 3)
                          | (fl[4][j] << 4) | (fl[5][j] << 5) | (fl[6][j] << 6) | (fl[7][j] << 7);
            if (byte) atomicOr(&sbitsT[tx * 4 + j][wsel], byte << shift);
        }
    }
    __syncthreads();
    {
        int r = t >> 1, w = t & 1;
        outb[(size_t)(by * 128 + r) * 32 + bx * 2 + w] = sbits[r][w];
    }
    {
        int r = t >> 2, w = t & 3;
        outbT[(size_t)(bx * 64 + r) * 32 + by * 4 + w] = sbitsT[r][w];
    }
}

// ---------------- 4. mask rows: warp per (row, segment) ---------------------
__global__ void k_mask_rows() {
    int g    = blockIdx.x * 8 + (threadIdx.x >> 5);
    int lane = threadIdx.x & 31;
    int u = g >> 2, s = g & 3;
    int b = u >> 10, ur = u & 1023;
    unsigned aown = g_Dbits[(size_t)b * NBLK * 32 + (size_t)ur * 32 + lane];
    unsigned* dst = g_maskbits + (size_t)u * 128 + s * 32 + lane;
    if (s == b) { *dst = aown; return; }
    const unsigned* P = (b < s) ? (g_ETbits + (size_t)(s - 1) * NBLK * 32)
                                : (g_Ebits  + (size_t)(b - 1) * NBLK * 32);
    unsigned acc = 0, acc2 = 0;
    for (int w = 0; w < 32; w++) {
        unsigned aw = __shfl_sync(0xffffffffu, aown, w);
        int vbase = w * 32;
        while (aw) {
            int bp1 = __ffs(aw) - 1; aw &= aw - 1;
            unsigned x1 = P[(size_t)(vbase + bp1) * 32 + lane];
            if (aw) {
                int bp2 = __ffs(aw) - 1; aw &= aw - 1;
                acc2 |= P[(size_t)(vbase + bp2) * 32 + lane];
            }
            acc |= x1;
        }
    }
    *dst = acc | acc2;
}

// ---------------- 5. bit transpose full mask --------------------------------
__global__ void k_bt_mask() {
    int lane = threadIdx.x & 31;
    int by   = blockIdx.y * 8 + (threadIdx.x >> 5);
    unsigned w = g_maskbits[(size_t)(by * 32 + lane) * 128 + blockIdx.x];
    #pragma unroll
    for (int c = 0; c < 32; c++) {
        unsigned bw = __ballot_sync(0xffffffffu, (w >> c) & 1u);
        if (lane == c) g_maskTbits[(size_t)(blockIdx.x * 32 + c) * 128 + by] = bw;
    }
}

// ---------------- 6. degrees + norm factors ---------------------------------
__global__ void k_degrees() {
    int u = blockIdx.x * blockDim.x + threadIdx.x;
    int p1 = 0, p2 = 0;
    for (int w = 0; w < 128; w++) {
        p2 += __popc(g_maskbits[(size_t)u * 128 + w]);
        p1 += __popc(g_maskTbits[(size_t)u * 128 + w]);
    }
    float n1 = p1 > 0 ? 1.0f / sqrtf((float)p1) : 0.0f;
    float i1 = p1 > 0 ? 1.0f / (float)p1 : 0.0f;
    g_a1[u] = n1; g_s1[u] = n1 * i1;
    float n2 = p2 > 0 ? 1.0f / sqrtf((float)p2) : 0.0f;
    float i2 = p2 > 0 ? 1.0f / (float)p2 : 0.0f;
    g_a2[u] = n2; g_s2[u] = n2 * i2;
}

// ---------------- 7a. layer-1 SpMM pair (z selects graph) -------------------
__global__ void k_spmm_dual(const unsigned* __restrict__ bits0,
                            const unsigned* __restrict__ bits1,
                            const float* __restrict__ feat,
                            const float* __restrict__ cs0, const float* __restrict__ cs1,
                            const float* __restrict__ rs0, const float* __restrict__ rs1,
                            float* __restrict__ out0, float* __restrict__ out1) {
    const unsigned* bits = blockIdx.z ? bits1 : bits0;
    const float* colscale = blockIdx.z ? cs1 : cs0;
    const float* rowscale = blockIdx.z ? rs1 : rs0;
    float* out = blockIdx.z ? out1 : out0;

    int u    = blockIdx.x * 8 + (threadIdx.x >> 5);
    int lane = threadIdx.x & 31;
    int off  = lane * 4;
    unsigned w4[4];
    #pragma unroll
    for (int i = 0; i < 4; i++) w4[i] = bits[(size_t)u * 128 + i * 32 + lane];

    float4 acc1 = make_float4(0.f, 0.f, 0.f, 0.f);
    float4 acc2 = make_float4(0.f, 0.f, 0.f, 0.f);
    for (int wi = 0; wi < 128; wi++) {
        unsigned word = __shfl_sync(0xffffffffu, w4[wi >> 5], wi & 31);
        int vbase = wi * 32;
        while (word) {
            int b1 = __ffs(word) - 1; word &= word - 1;
            int v1 = vbase + b1;
            float  cs1v = __ldg(colscale + v1);
            float4 f1   = __ldg((const float4*)(feat + (size_t)v1 * NF + off));
            if (word) {
                int b2 = __ffs(word) - 1; word &= word - 1;
                int v2 = vbase + b2;
                float  cs2v = __ldg(colscale + v2);
                float4 f2   = __ldg((const float4*)(feat + (size_t)v2 * NF + off));
                acc2.x += cs2v * f2.x; acc2.y += cs2v * f2.y;
                acc2.z += cs2v * f2.z; acc2.w += cs2v * f2.w;
            }
            acc1.x += cs1v * f1.x; acc1.y += cs1v * f1.y;
            acc1.z += cs1v * f1.z; acc1.w += cs1v * f1.w;
        }
    }
    float rs = rowscale[u];
    float4 s = *(const float4*)(feat + (size_t)u * NF + off);
    float4 r;
    r.x = s.x + rs * (acc1.x + acc2.x);
    r.y = s.y + rs * (acc1.y + acc2.y);
    r.z = s.z + rs * (acc1.z + acc2.z);
    r.w = s.w + rs * (acc1.w + acc2.w);
    *(float4*)(out + (size_t)u * NF + off) = r;
}

// ---------------- 7b. layer-2 SpMM pair on transformed G, bias+relu ---------
// 2-wide edge fetch (proven R8 schedule).
__global__ void k_spmm_br_dual(const unsigned* __restrict__ bits0,
                               const unsigned* __restrict__ bits1,
                               const float* __restrict__ G0, const float* __restrict__ G1,
                               const float* __restrict__ cs0, const float* __restrict__ cs1,
                               const float* __restrict__ rs0, const float* __restrict__ rs1,
                               const float* __restrict__ bias0, const float* __restrict__ bias1,
                               float* __restrict__ out0, float* __restrict__ out1) {
    const unsigned* bits  = blockIdx.z ? bits1 : bits0;
    const float* G        = blockIdx.z ? G1 : G0;
    const float* colscale = blockIdx.z ? cs1 : cs0;
    const float* rowscale = blockIdx.z ? rs1 : rs0;
    const float* bias     = blockIdx.z ? bias1 : bias0;
    float* out            = blockIdx.z ? out1 : out0;

    int u    = blockIdx.x * 8 + (threadIdx.x >> 5);
    int lane = threadIdx.x & 31;
    int off  = blockIdx.y * 128 + lane * 4;
    unsigned w4[4];
    #pragma unroll
    for (int i = 0; i < 4; i++) w4[i] = bits[(size_t)u * 128 + i * 32 + lane];

    float4 acc1 = make_float4(0.f, 0.f, 0.f, 0.f);
    float4 acc2 = make_float4(0.f, 0.f, 0.f, 0.f);
    for (int wi = 0; wi < 128; wi++) {
        unsigned word = __shfl_sync(0xffffffffu, w4[wi >> 5], wi & 31);
        int vbase = wi * 32;
        while (word) {
            int b1 = __ffs(word) - 1; word &= word - 1;
            int v1 = vbase + b1;
            float  csa = __ldg(colscale + v1);
            float4 f1  = __ldg((const float4*)(G + (size_t)v1 * HF + off));
            if (word) {
                int b2 = __ffs(word) - 1; word &= word - 1;
                int v2 = vbase + b2;
                float  csb = __ldg(colscale + v2);
                float4 f2  = __ldg((const float4*)(G + (size_t)v2 * HF + off));
                acc2.x += csb * f2.x; acc2.y += csb * f2.y;
                acc2.z += csb * f2.z; acc2.w += csb * f2.w;
            }
            acc1.x += csa * f1.x; acc1.y += csa * f1.y;
            acc1.z += csa * f1.z; acc1.w += csa * f1.w;
        }
    }
    float rs = rowscale[u];
    float4 s  = *(const float4*)(G + (size_t)u * HF + off);
    float4 bb = *(const float4*)(bias + off);
    float4 r;
    r.x = fmaxf(s.x + rs * (acc1.x + acc2.x) + bb.x, 0.0f);
    r.y = fmaxf(s.y + rs * (acc1.y + acc2.y) + bb.y, 0.0f);
    r.z = fmaxf(s.z + rs * (acc1.z + acc2.z) + bb.z, 0.0f);
    r.w = fmaxf(s.w + rs * (acc1.w + acc2.w) + bb.w, 0.0f);
    *(float4*)(out + (size_t)u * HH + off) = r;
}

// ---------------- 8. tf32 GEMM pair, 64x128 tile, double-buffered loads -----
// 8 warps (2x4), warp tile 32x32 (2x2 wmma m16n16k8 frags). Grid 2x64x2 = 256
// blocks (~2/SM). Bias preloaded into accumulators; relu on fragments; direct
// global store. Global loads for chunk c+1 issued before the mma loop on c.
#define TCM 64
#define TCN 128
#define TCK 32
#define LDA 36
#define LDB 132
template<int RELU, int KSCALE>
__global__ void k_gemm2_tc(const float* __restrict__ A0, const float* __restrict__ A1,
                           const float* __restrict__ B0, const float* __restrict__ B1,
                           const float* __restrict__ bias0, const float* __restrict__ bias1,
                           const float* __restrict__ kscale,
                           float* __restrict__ C0, float* __restrict__ C1,
                           int K, int ldc, int coff) {
    const float* A    = blockIdx.z ? A1 : A0;
    const float* B    = blockIdx.z ? B1 : B0;
    const float* bias = blockIdx.z ? bias1 : bias0;
    float* Cb = (blockIdx.z ? C1 : C0) + coff * blockIdx.z;

    __shared__ __align__(16) float As[TCM * LDA];      // 2304 floats
    __shared__ __align__(16) float Bs[TCK * LDB];      // 4224
    __shared__ __align__(16) float BiasS[16 * LDB];    // 2112

    int t   = threadIdx.x;
    int wid = t >> 5;
    int wm  = wid & 1, wn = wid >> 1;     // 2 x 4 warp grid, warp tile 32x32
    int row0 = blockIdx.y * TCM, col0 = blockIdx.x * TCN;

    // stage replicated bias tile (16 rows x 128 cols)
    #pragma unroll
    for (int i = 0; i < 8; i++) {
        int idx = t + i * 256;
        int r = idx >> 7, cc = idx & 127;
        BiasS[r * LDB + cc] = bias[col0 + cc];
    }
    __syncthreads();

    wmma::fragment<wmma::accumulator, 16, 16, 8, float> c[2][2];
    #pragma unroll
    for (int i = 0; i < 2; i++)
        #pragma unroll
        for (int j = 0; j < 2; j++)
            wmma::load_matrix_sync(c[i][j], BiasS + wn * 32 + j * 16, LDB, wmma::mem_row_major);

    int ar = t >> 2, ac = (t & 3) * 8;      // A: 64 rows x 32 k (2 float4/thr)
    int br = t >> 3, bc = (t & 7) * 16;     // B: 32 rows x 128 cols (4 float4/thr)
    int NC = K / TCK;

    float4 aR[2], bR[4];
    float scR = 1.0f;
    {   // prefetch chunk 0
        const float* Ap = A + (size_t)(row0 + ar) * K + ac;
        aR[0] = *(const float4*)(Ap);
        aR[1] = *(const float4*)(Ap + 4);
        if (KSCALE) scR = kscale[br];
        const float* Bp = B + (size_t)br * HF + col0 + bc;
        #pragma unroll
        for (int m = 0; m < 4; m++) bR[m] = *(const float4*)(Bp + m * 4);
    }

    for (int ci = 0; ci < NC; ci++) {
        // store prefetched chunk to smem (with tf32 convert + kscale)
        {
            float* d = As + ar * LDA + ac;
            d[0] = to_tf32(aR[0].x); d[1] = to_tf32(aR[0].y);
            d[2] = to_tf32(aR[0].z); d[3] = to_tf32(aR[0].w);
            d[4] = to_tf32(aR[1].x); d[5] = to_tf32(aR[1].y);
            d[6] = to_tf32(aR[1].z); d[7] = to_tf32(aR[1].w);
            float sc = KSCALE ? scR : 1.0f;
            float* e = Bs + br * LDB + bc;
            #pragma unroll
            for (int m = 0; m < 4; m++) {
                e[m * 4 + 0] = to_tf32(bR[m].x * sc);
                e[m * 4 + 1] = to_tf32(bR[m].y * sc);
                e[m * 4 + 2] = to_tf32(bR[m].z * sc);
                e[m * 4 + 3] = to_tf32(bR[m].w * sc);
            }
        }
        __syncthreads();
        // prefetch next chunk while mma runs
        if (ci + 1 < NC) {
            int k0 = (ci + 1) * TCK;
            const float* Ap = A + (size_t)(row0 + ar) * K + k0 + ac;
            aR[0] = *(const float4*)(Ap);
            aR[1] = *(const float4*)(Ap + 4);
            if (KSCALE) scR = kscale[k0 + br];
            const float* Bp = B + (size_t)(k0 + br) * HF + col0 + bc;
            #pragma unroll
            for (int m = 0; m < 4; m++) bR[m] = *(const float4*)(Bp + m * 4);
        }
        #pragma unroll
        for (int kk = 0; kk < TCK; kk += 8) {
            wmma::fragment<wmma::matrix_a, 16, 16, 8, wmma::precision::tf32, wmma::row_major> a[2];
            wmma::fragment<wmma::matrix_b, 16, 16, 8, wmma::precision::tf32, wmma::row_major> b[2];
            #pragma unroll
            for (int i = 0; i < 2; i++)
                wmma::load_matrix_sync(a[i], As + (wm * 32 + i * 16) * LDA + kk, LDA);
            #pragma unroll
            for (int j = 0; j < 2; j++)
                wmma::load_matrix_sync(b[j], Bs + kk * LDB + wn * 32 + j * 16, LDB);
            #pragma unroll
            for (int i = 0; i < 2; i++)
                #pragma unroll
                for (int j = 0; j < 2; j++)
                    wmma::mma_sync(c[i][j], a[i], b[j], c[i][j]);
        }
        if (ci + 1 < NC) __syncthreads();
    }
    // epilogue: relu on fragments, store directly to global
    #pragma unroll
    for (int i = 0; i < 2; i++)
        #pragma unroll
        for (int j = 0; j < 2; j++) {
            if (RELU) {
                #pragma unroll
                for (int e = 0; e < c[i][j].num_elements; e++)
                    c[i][j].x[e] = fmaxf(c[i][j].x[e], 0.0f);
            }
            wmma::store_matrix_sync(
                Cb + (size_t)(row0 + wm * 32 + i * 16) * ldc + col0 + wn * 32 + j * 16,
                c[i][j], ldc, wmma::mem_row_major);
        }
}

// ---------------- 9. single-pass batchnorm stats -> scale/offset ------------
__global__ void k_bn_stats(const float* __restrict__ H,
                           const float* __restrict__ gamma,
                           const float* __restrict__ beta,
                           float* __restrict__ scol, float* __restrict__ ccol) {
    int tx = threadIdx.x, ty = threadIdx.y;
    int c = blockIdx.x * 32 + tx;
    __shared__ float redS[8][32], redQ[8][32];
    float s = 0.f, q = 0.f;
    for (int r = ty; r < BS; r += 8) {
        float v = H[(size_t)r * HH + c];
        s += v; q += v * v;
    }
    redS[ty][tx] = s; redQ[ty][tx] = q; __syncthreads();
    if (ty == 0) {
        float ts = 0.f, tq = 0.f;
        #pragma unroll
        for (int y = 0; y < 8; y++) { ts += redS[y][tx]; tq += redQ[y][tx]; }
        float mu  = ts * (1.0f / BS);
        float var = tq * (1.0f / BS) - mu * mu;
        float sc  = gamma[c] * rsqrtf(var + 1e-5f);
        scol[c] = sc;
        ccol[c] = beta[c] - mu * sc;
    }
}

// ---------------- 9b. rank-1 BN bias rows: R_z = c1 @ W2_z ------------------
__global__ void k_Rrow(const float* __restrict__ wAC2, const float* __restrict__ wCA2) {
    int c = blockIdx.x * 256 + threadIdx.x;   // 0..511
    const float* W = (c < HF) ? wAC2 : wCA2;
    int cc = c & (HF - 1);
    float acc = 0.f;
    for (int k = 0; k < HH; k++) acc += g_c1[k] * W[(size_t)k * HF + cc];
    if (c < HF) g_R1[cc] = acc; else g_R2[cc] = acc;
}

// ---------------- 10. fused BN2 + readout + softmax + modality mix ----------
__global__ void k_final2(const float* __restrict__ w_ro,
                         const float* __restrict__ cmix,
                         float* __restrict__ out) {
    int node = blockIdx.x * 8 + (threadIdx.x >> 5);
    int lane = threadIdx.x & 31;
    float m  = fmaxf(fmaxf(cmix[0], cmix[1]), fmaxf(cmix[2], cmix[3]));
    float e0 = expf(cmix[0] - m), e1 = expf(cmix[1] - m);
    float e2 = expf(cmix[2] - m), e3 = expf(cmix[3] - m);
    float inv = 1.0f / (e0 + e1 + e2 + e3);
    float w0 = e0 * inv, w1 = e1 * inv, w2 = e2 * inv, w3 = e3 * inv;

    float a0 = 0, a1 = 0, a2 = 0, a3 = 0;
    for (int f = lane; f < HH; f += 32) {
        float hsum = w0 * g_h[(size_t)(0 * NBLK + node) * HH + f]
                   + w1 * g_h[(size_t)(1 * NBLK + node) * HH + f]
                   + w2 * g_h[(size_t)(2 * NBLK + node) * HH + f]
                   + w3 * g_h[(size_t)(3 * NBLK + node) * HH + f];
        float x = g_s2col[f] * hsum + g_c2[f];   // weights sum to 1
        a0 += x * w_ro[f * 4 + 0];
        a1 += x * w_ro[f * 4 + 1];
        a2 += x * w_ro[f * 4 + 2];
        a3 += x * w_ro[f * 4 + 3];
    }
    #pragma unroll
    for (int o = 16; o; o >>= 1) {
        a0 += __shfl_xor_sync(0xffffffffu, a0, o);
        a1 += __shfl_xor_sync(0xffffffffu, a1, o);
        a2 += __shfl_xor_sync(0xffffffffu, a2, o);
        a3 += __shfl_xor_sync(0xffffffffu, a3, o);
    }
    if (lane == 0) {
        out[node * 4 + 0] = a0; out[node * 4 + 1] = a1;
        out[node * 4 + 2] = a2; out[node * 4 + 3] = a3;
    }
}

// ---------------- launch -----------------------------------------------------
extern "C" void kernel_launch(void* const* d_in, const int* in_sizes, int n_in,
                              void* d_out, int out_size) {
    (void)in_sizes; (void)n_in; (void)out_size;
    const float* features = (const float*)d_in[0];
    const float* sparse   = (const float*)d_in[1];
    const float* cmix     = (const float*)d_in[2];
    const float* wAC1     = (const float*)d_in[3];
    const float* bAC1     = (const float*)d_in[4];
    const float* wCA1     = (const float*)d_in[5];
    const float* bCA1     = (const float*)d_in[6];
    const float* wAC2     = (const float*)d_in[7];
    const float* bAC2     = (const float*)d_in[8];
    const float* wCA2     = (const float*)d_in[9];
    const float* bCA2     = (const float*)d_in[10];
    const float* gamma1   = (const float*)d_in[11];
    const float* beta1    = (const float*)d_in[12];
    const float* gamma2   = (const float*)d_in[13];
    const float* beta2    = (const float*)d_in[14];
    const float* w_ro     = (const float*)d_in[15];
    float* out = (float*)d_out;

    float*    Z1  = nullptr; cudaGetSymbolAddress((void**)&Z1,  g_Z1);
    float*    Z2  = nullptr; cudaGetSymbolAddress((void**)&Z2,  g_Z2);
    float*    H   = nullptr; cudaGetSymbolAddress((void**)&H,   g_h);
    float*    A1  = nullptr; cudaGetSymbolAddress((void**)&A1,  g_a1);
    float*    S1  = nullptr; cudaGetSymbolAddress((void**)&S1,  g_s1);
    float*    A2  = nullptr; cudaGetSymbolAddress((void**)&A2,  g_a2);
    float*    S2  = nullptr; cudaGetSymbolAddress((void**)&S2,  g_s2);
    unsigned* MB  = nullptr; cudaGetSymbolAddress((void**)&MB,  g_maskbits);
    unsigned* MTB = nullptr; cudaGetSymbolAddress((void**)&MTB, g_maskTbits);
    float*    S1C = nullptr; cudaGetSymbolAddress((void**)&S1C, g_s1col);
    float*    C1  = nullptr; cudaGetSymbolAddress((void**)&C1,  g_c1);
    float*    S2C = nullptr; cudaGetSymbolAddress((void**)&S2C, g_s2col);
    float*    C2  = nullptr; cudaGetSymbolAddress((void**)&C2,  g_c2);
    float*    R1  = nullptr; cudaGetSymbolAddress((void**)&R1,  g_R1);
    float*    R2  = nullptr; cudaGetSymbolAddress((void**)&R2,  g_R2);

    k_rownorm<<<BS / 8, 256>>>(features);
    k_corr_ind<<<dim3(16, 8, 7), 256>>>(sparse);
    k_mask_rows<<<2048, 256>>>();
    k_bt_mask<<<dim3(128, 16), 256>>>();
    k_degrees<<<16, 256>>>();

    // layer 1: aggregate-first, then tf32 GEMM pair with bias+relu
    k_spmm_dual<<<dim3(BS / 8, 1, 2), 256>>>(MTB, MB, features,
                                             A1, A2, S1, S2, Z1, Z2);
    k_gemm2_tc<1, 0><<<dim3(HF / TCN, BS / TCM, 2), 256>>>(
        Z1, Z2, wAC1, wCA1, bAC1, bCA1, nullptr, H, H, NF, HH, HF);
    k_bn_stats<<<HH / 32, dim3(32, 8)>>>(H, gamma1, beta1, S1C, C1);
    k_Rrow<<<2, 256>>>(wAC2, wCA2);

    // layer 2: BN1 folded into GEMM (kscale=s1col, bias=R_z), then SpMM+bias+relu
    k_gemm2_tc<0, 1><<<dim3(HF / TCN, BS / TCM, 2), 256>>>(
        H, H, wAC2, wCA2, R1, R2, S1C, Z1, Z2, HH, HF, 0);
    k_spmm_br_dual<<<dim3(BS / 8, 2, 2), 256>>>(MTB, MB, Z1, Z2,
                                                A1, A2, S1, S2, bAC2, bCA2, H, H + HF);
    k_bn_stats<<<HH / 32, dim3(32, 8)>>>(H, gamma2, beta2, S2C, C2);

    k_final2<<<NBLK / 8, 256>>>(w_ro, cmix, out);
}

// round 17
// speedup vs baseline: 1.0820x; 1.0820x over previous
#include <cuda_runtime.h>
#include <math.h>
#include <stdint.h>
#include <mma.h>
using namespace nvcuda;

// Problem constants
#define BS 4096
#define NF 128
#define HF 256
#define HH 512          // 2*HF
#define NBLK 1024       // n = BS/M
#define NCLS 4

// ---------------- scratch ----------------------------------------------------
__device__ float    g_Y[BS * NF];                 // row-normalized features
__device__ unsigned g_Dbits[4 * NBLK * 32];       // diag block indicators (A)
__device__ unsigned g_Ebits[3 * NBLK * 32];       // B03,B13,B23 indicators
__device__ unsigned g_ETbits[3 * NBLK * 32];      // their bit-transposes
__device__ unsigned g_maskbits[BS * 128];         // mask rows, bit packed
__device__ unsigned g_maskTbits[BS * 128];        // mask^T rows, bit packed
__device__ float    g_a1[BS], g_s1[BS], g_a2[BS], g_s2[BS];
__device__ float    g_Z1[BS * HH];                // scratch
__device__ float    g_Z2[BS * HH];
__device__ float    g_h[BS * HH];                 // concat gin outputs
__device__ float    g_s1col[HH], g_c1[HH];        // BN1 scale / offset per col
__device__ float    g_s2col[HH], g_c2[HH];        // BN2 scale / offset per col
__device__ float    g_R1[HF], g_R2[HF];           // c1 @ W2 rank-1 bias rows

__device__ __forceinline__ float to_tf32(float x) {
    float r;
    asm("cvt.rna.tf32.f32 %0, %1;" : "=f"(r) : "f"(x));
    return r;
}

// ---------------- 1. row-normalize features ---------------------------------
__global__ void k_rownorm(const float* __restrict__ F) {
    int u    = blockIdx.x * 8 + (threadIdx.x >> 5);
    int lane = threadIdx.x & 31;
    float4 v = *(const float4*)(F + (size_t)u * NF + lane * 4);
    float s = v.x + v.y + v.z + v.w;
    #pragma unroll
    for (int o = 16; o; o >>= 1) s += __shfl_xor_sync(0xffffffffu, s, o);
    float m = s * (1.0f / NF);
    v.x -= m; v.y -= m; v.z -= m; v.w -= m;
    float ss = v.x*v.x + v.y*v.y + v.z*v.z + v.w*v.w;
    #pragma unroll
    for (int o = 16; o; o >>= 1) ss += __shfl_xor_sync(0xffffffffu, ss, o);
    float inv = 1.0f / sqrtf(ss);
    v.x *= inv; v.y *= inv; v.z *= inv; v.w *= inv;
    *(float4*)(g_Y + (size_t)u * NF + lane * 4) = v;
}

// ---------------- 2. correlation block indicators (128x64 tiles, 8x4/thr) ---
__global__ void k_corr_ind(const float* __restrict__ sparse) {
    const int t_bi[7]  = {0, 1, 2, 3, 0, 1, 2};
    const int t_bj[7]  = {0, 1, 2, 3, 3, 3, 3};
    const int t_cnt[7] = {1, 5, 8, 10, 4, 7, 9};
    int z  = blockIdx.z;
    int by = blockIdx.y;          // 0..7  (128-row tiles)
    int bx = blockIdx.x;          // 0..15 (64-col tiles)
    bool diag = (z < 4);
    if (diag && bx < 2 * by) return;          // fully below diagonal
    int bi = t_bi[z], bj = t_bj[z];
    float thr = 1.0f / (1.0f + expf(-sparse[t_cnt[z]]));
    unsigned* outb  = diag ? (g_Dbits + (size_t)z * NBLK * 32)
                           : (g_Ebits + (size_t)(z - 4) * NBLK * 32);
    unsigned* outbT = diag ? outb
                           : (g_ETbits + (size_t)(z - 4) * NBLK * 32);

    __shared__ __align__(16) float Ut[32][136];   // [k_local][row 0..127]
    __shared__ __align__(16) float Vt[32][72];    // [k_local][col 0..63]
    __shared__ unsigned sbits[128][2];
    __shared__ unsigned sbitsT[64][4];

    int t  = threadIdx.x;
    int tx = t & 15, ty = t >> 4;
    int u0 = bi * NBLK + by * 128;
    int v0 = bj * NBLK + bx * 64;

    sbits[t >> 1][t & 1]  = 0u;
    sbitsT[t >> 2][t & 3] = 0u;

    float acc[8][4] = {};
    int lrA = t >> 1, lqA = t & 1;   // A load: row, 16-k half
    int lrB = t >> 2, lqB = t & 3;   // B load: row, 8-k quarter
    #pragma unroll
    for (int pass = 0; pass < 4; pass++) {
        int k0 = pass * 32;
        if (pass) __syncthreads();
        #pragma unroll
        for (int m = 0; m < 4; m++) {
            int c = lqA * 16 + m * 4;
            float4 a = *(const float4*)(g_Y + (size_t)(u0 + lrA) * NF + k0 + c);
            Ut[c + 0][lrA] = a.x; Ut[c + 1][lrA] = a.y;
            Ut[c + 2][lrA] = a.z; Ut[c + 3][lrA] = a.w;
        }
        #pragma unroll
        for (int m = 0; m < 2; m++) {
            int c = lqB * 8 + m * 4;
            float4 b = *(const float4*)(g_Y + (size_t)(v0 + lrB) * NF + k0 + c);
            Vt[c + 0][lrB] = b.x; Vt[c + 1][lrB] = b.y;
            Vt[c + 2][lrB] = b.z; Vt[c + 3][lrB] = b.w;
        }
        __syncthreads();
        #pragma unroll 8
        for (int k = 0; k < 32; k++) {
            float4 a0 = *(const float4*)&Ut[k][ty * 8];
            float4 a1 = *(const float4*)&Ut[k][ty * 8 + 4];
            float4 b  = *(const float4*)&Vt[k][tx * 4];
            acc[0][0]+=a0.x*b.x; acc[0][1]+=a0.x*b.y; acc[0][2]+=a0.x*b.z; acc[0][3]+=a0.x*b.w;
            acc[1][0]+=a0.y*b.x; acc[1][1]+=a0.y*b.y; acc[1][2]+=a0.y*b.z; acc[1][3]+=a0.y*b.w;
            acc[2][0]+=a0.z*b.x; acc[2][1]+=a0.z*b.y; acc[2][2]+=a0.z*b.z; acc[2][3]+=a0.z*b.w;
            acc[3][0]+=a0.w*b.x; acc[3][1]+=a0.w*b.y; acc[3][2]+=a0.w*b.z; acc[3][3]+=a0.w*b.w;
            acc[4][0]+=a1.x*b.x; acc[4][1]+=a1.x*b.y; acc[4][2]+=a1.x*b.z; acc[4][3]+=a1.x*b.w;
            acc[5][0]+=a1.y*b.x; acc[5][1]+=a1.y*b.y; acc[5][2]+=a1.y*b.z; acc[5][3]+=a1.y*b.w;
            acc[6][0]+=a1.z*b.x; acc[6][1]+=a1.z*b.y; acc[6][2]+=a1.z*b.z; acc[6][3]+=a1.z*b.w;
            acc[7][0]+=a1.w*b.x; acc[7][1]+=a1.w*b.y; acc[7][2]+=a1.w*b.z; acc[7][3]+=a1.w*b.w;
        }
    }
    // threshold -> flags
    unsigned fl[8][4];
    #pragma unroll
    for (int i = 0; i < 8; i++) {
        int gu = u0 + ty * 8 + i;
        #pragma unroll
        for (int j = 0; j < 4; j++) {
            int gv = v0 + tx * 4 + j;
            float g  = fminf(fmaxf(acc[i][j], -1.0f), 1.0f);
            float aw = fabsf(g) - ((gu == gv) ? 1.0f : 0.0f);
            fl[i][j] = ((aw - thr) > 0.0f) ? 1u : 0u;
        }
    }
    {
        int wsel = tx >> 3, shift = (tx & 7) * 4;
        #pragma unroll
        for (int i = 0; i < 8; i++) {
            unsigned nib = fl[i][0] | (fl[i][1] << 1) | (fl[i][2] << 2) | (fl[i][3] << 3);
            if (nib) atomicOr(&sbits[ty * 8 + i][wsel], nib << shift);
        }
    }
    {
        int wsel = ty >> 2, shift = (ty & 3) * 8;
        #pragma unroll
        for (int j = 0; j < 4; j++) {
            unsigned byte = fl[0][j] | (fl[1][j] << 1) | (fl[2][j] << 2) | (fl[3][j] << 3)
                          | (fl[4][j] << 4) | (fl[5][j] << 5) | (fl[6][j] << 6) | (fl[7][j] << 7);
            if (byte) atomicOr(&sbitsT[tx * 4 + j][wsel], byte << shift);
        }
    }
    __syncthreads();
    {
        int r = t >> 1, w = t & 1;
        outb[(size_t)(by * 128 + r) * 32 + bx * 2 + w] = sbits[r][w];
    }
    {
        int r = t >> 2, w = t & 3;
        outbT[(size_t)(bx * 64 + r) * 32 + by * 4 + w] = sbitsT[r][w];
    }
}

// ---------------- 4. mask rows: warp per (row, segment), sparse word skip ---
__global__ void k_mask_rows() {
    int g    = blockIdx.x * 8 + (threadIdx.x >> 5);
    int lane = threadIdx.x & 31;
    int u = g >> 2, s = g & 3;
    int b = u >> 10, ur = u & 1023;
    unsigned aown = g_Dbits[(size_t)b * NBLK * 32 + (size_t)ur * 32 + lane];
    unsigned* dst = g_maskbits + (size_t)u * 128 + s * 32 + lane;
    if (s == b) { *dst = aown; return; }
    const unsigned* P = (b < s) ? (g_ETbits + (size_t)(s - 1) * NBLK * 32)
                                : (g_Ebits  + (size_t)(b - 1) * NBLK * 32);
    unsigned acc = 0, acc2 = 0;
    unsigned ne = __ballot_sync(0xffffffffu, aown != 0u);
    while (ne) {
        int src = __ffs(ne) - 1; ne &= ne - 1;
        unsigned aw = __shfl_sync(0xffffffffu, aown, src);
        int vbase = src * 32;
        while (aw) {
            int bp1 = __ffs(aw) - 1; aw &= aw - 1;
            unsigned x1 = P[(size_t)(vbase + bp1) * 32 + lane];
            if (aw) {
                int bp2 = __ffs(aw) - 1; aw &= aw - 1;
                acc2 |= P[(size_t)(vbase + bp2) * 32 + lane];
            }
            acc |= x1;
        }
    }
    *dst = acc | acc2;
}

// ---------------- 5. bit transpose full mask --------------------------------
__global__ void k_bt_mask() {
    int lane = threadIdx.x & 31;
    int by   = blockIdx.y * 8 + (threadIdx.x >> 5);
    unsigned w = g_maskbits[(size_t)(by * 32 + lane) * 128 + blockIdx.x];
    #pragma unroll
    for (int c = 0; c < 32; c++) {
        unsigned bw = __ballot_sync(0xffffffffu, (w >> c) & 1u);
        if (lane == c) g_maskTbits[(size_t)(blockIdx.x * 32 + c) * 128 + by] = bw;
    }
}

// ---------------- 6. degrees + norm factors ---------------------------------
__global__ void k_degrees() {
    int u = blockIdx.x * blockDim.x + threadIdx.x;
    int p1 = 0, p2 = 0;
    for (int w = 0; w < 128; w++) {
        p2 += __popc(g_maskbits[(size_t)u * 128 + w]);
        p1 += __popc(g_maskTbits[(size_t)u * 128 + w]);
    }
    float n1 = p1 > 0 ? 1.0f / sqrtf((float)p1) : 0.0f;
    float i1 = p1 > 0 ? 1.0f / (float)p1 : 0.0f;
    g_a1[u] = n1; g_s1[u] = n1 * i1;
    float n2 = p2 > 0 ? 1.0f / sqrtf((float)p2) : 0.0f;
    float i2 = p2 > 0 ? 1.0f / (float)p2 : 0.0f;
    g_a2[u] = n2; g_s2[u] = n2 * i2;
}

// ---------------- 7a. layer-1 SpMM pair, sparse word skip -------------------
__global__ void k_spmm_dual(const unsigned* __restrict__ bits0,
                            const unsigned* __restrict__ bits1,
                            const float* __restrict__ feat,
                            const float* __restrict__ cs0, const float* __restrict__ cs1,
                            const float* __restrict__ rs0, const float* __restrict__ rs1,
                            float* __restrict__ out0, float* __restrict__ out1) {
    const unsigned* bits = blockIdx.z ? bits1 : bits0;
    const float* colscale = blockIdx.z ? cs1 : cs0;
    const float* rowscale = blockIdx.z ? rs1 : rs0;
    float* out = blockIdx.z ? out1 : out0;

    int u    = blockIdx.x * 8 + (threadIdx.x >> 5);
    int lane = threadIdx.x & 31;
    int off  = lane * 4;
    unsigned w4[4];
    #pragma unroll
    for (int i = 0; i < 4; i++) w4[i] = bits[(size_t)u * 128 + i * 32 + lane];

    float4 acc1 = make_float4(0.f, 0.f, 0.f, 0.f);
    float4 acc2 = make_float4(0.f, 0.f, 0.f, 0.f);
    #pragma unroll
    for (int gi = 0; gi < 4; gi++) {
        unsigned ne = __ballot_sync(0xffffffffu, w4[gi] != 0u);
        while (ne) {
            int src = __ffs(ne) - 1; ne &= ne - 1;
            unsigned word = __shfl_sync(0xffffffffu, w4[gi], src);
            int vbase = (gi * 32 + src) * 32;
            while (word) {
                int b1 = __ffs(word) - 1; word &= word - 1;
                int v1 = vbase + b1;
                float  cs1v = __ldg(colscale + v1);
                float4 f1   = __ldg((const float4*)(feat + (size_t)v1 * NF + off));
                if (word) {
                    int b2 = __ffs(word) - 1; word &= word - 1;
                    int v2 = vbase + b2;
                    float  cs2v = __ldg(colscale + v2);
                    float4 f2   = __ldg((const float4*)(feat + (size_t)v2 * NF + off));
                    acc2.x += cs2v * f2.x; acc2.y += cs2v * f2.y;
                    acc2.z += cs2v * f2.z; acc2.w += cs2v * f2.w;
                }
                acc1.x += cs1v * f1.x; acc1.y += cs1v * f1.y;
                acc1.z += cs1v * f1.z; acc1.w += cs1v * f1.w;
            }
        }
    }
    float rs = rowscale[u];
    float4 s = *(const float4*)(feat + (size_t)u * NF + off);
    float4 r;
    r.x = s.x + rs * (acc1.x + acc2.x);
    r.y = s.y + rs * (acc1.y + acc2.y);
    r.z = s.z + rs * (acc1.z + acc2.z);
    r.w = s.w + rs * (acc1.w + acc2.w);
    *(float4*)(out + (size_t)u * NF + off) = r;
}

// ---------------- 7b. layer-2 SpMM pair, bias+relu, sparse word skip --------
__global__ void k_spmm_br_dual(const unsigned* __restrict__ bits0,
                               const unsigned* __restrict__ bits1,
                               const float* __restrict__ G0, const float* __restrict__ G1,
                               const float* __restrict__ cs0, const float* __restrict__ cs1,
                               const float* __restrict__ rs0, const float* __restrict__ rs1,
                               const float* __restrict__ bias0, const float* __restrict__ bias1,
                               float* __restrict__ out0, float* __restrict__ out1) {
    const unsigned* bits  = blockIdx.z ? bits1 : bits0;
    const float* G        = blockIdx.z ? G1 : G0;
    const float* colscale = blockIdx.z ? cs1 : cs0;
    const float* rowscale = blockIdx.z ? rs1 : rs0;
    const float* bias     = blockIdx.z ? bias1 : bias0;
    float* out            = blockIdx.z ? out1 : out0;

    int u    = blockIdx.x * 8 + (threadIdx.x >> 5);
    int lane = threadIdx.x & 31;
    int off  = blockIdx.y * 128 + lane * 4;
    unsigned w4[4];
    #pragma unroll
    for (int i = 0; i < 4; i++) w4[i] = bits[(size_t)u * 128 + i * 32 + lane];

    float4 acc1 = make_float4(0.f, 0.f, 0.f, 0.f);
    float4 acc2 = make_float4(0.f, 0.f, 0.f, 0.f);
    #pragma unroll
    for (int gi = 0; gi < 4; gi++) {
        unsigned ne = __ballot_sync(0xffffffffu, w4[gi] != 0u);
        while (ne) {
            int src = __ffs(ne) - 1; ne &= ne - 1;
            unsigned word = __shfl_sync(0xffffffffu, w4[gi], src);
            int vbase = (gi * 32 + src) * 32;
            while (word) {
                int b1 = __ffs(word) - 1; word &= word - 1;
                int v1 = vbase + b1;
                float  csa = __ldg(colscale + v1);
                float4 f1  = __ldg((const float4*)(G + (size_t)v1 * HF + off));
                if (word) {
                    int b2 = __ffs(word) - 1; word &= word - 1;
                    int v2 = vbase + b2;
                    float  csb = __ldg(colscale + v2);
                    float4 f2  = __ldg((const float4*)(G + (size_t)v2 * HF + off));
                    acc2.x += csb * f2.x; acc2.y += csb * f2.y;
                    acc2.z += csb * f2.z; acc2.w += csb * f2.w;
                }
                acc1.x += csa * f1.x; acc1.y += csa * f1.y;
                acc1.z += csa * f1.z; acc1.w += csa * f1.w;
            }
        }
    }
    float rs = rowscale[u];
    float4 s  = *(const float4*)(G + (size_t)u * HF + off);
    float4 bb = *(const float4*)(bias + off);
    float4 r;
    r.x = fmaxf(s.x + rs * (acc1.x + acc2.x) + bb.x, 0.0f);
    r.y = fmaxf(s.y + rs * (acc1.y + acc2.y) + bb.y, 0.0f);
    r.z = fmaxf(s.z + rs * (acc1.z + acc2.z) + bb.z, 0.0f);
    r.w = fmaxf(s.w + rs * (acc1.w + acc2.w) + bb.w, 0.0f);
    *(float4*)(out + (size_t)u * HH + off) = r;
}

// ---------------- 8. tf32 tensor-core GEMM pair (R8 best-measured config) ----
// Block tile 128x64, BK=32, 8 warps (4x2), warp tile 32x32 (2x2 wmma m16n16k8).
#define TCM 128
#define TCN 64
#define TCK 32
#define LDA 36
#define LDB 68
template<int RELU, int KSCALE>
__global__ void k_gemm2_tc(const float* __restrict__ A0, const float* __restrict__ A1,
                           const float* __restrict__ B0, const float* __restrict__ B1,
                           const float* __restrict__ bias0, const float* __restrict__ bias1,
                           const float* __restrict__ kscale,
                           float* __restrict__ C0, float* __restrict__ C1,
                           int K, int ldc, int coff) {
    const float* A    = blockIdx.z ? A1 : A0;
    const float* B    = blockIdx.z ? B1 : B0;
    const float* bias = blockIdx.z ? bias1 : bias0;
    float* Cb = (blockIdx.z ? C1 : C0) + coff * blockIdx.z;

    __shared__ __align__(16) float buf[8192];    // staging 6784 / epilogue 8192
    float* As = buf;                             // [128][36]
    float* Bs = buf + TCM * LDA;                 // [32][68]

    int t   = threadIdx.x;
    int wid = t >> 5;
    int wm  = wid & 3, wn = wid >> 2;
    int row0 = blockIdx.y * TCM, col0 = blockIdx.x * TCN;

    wmma::fragment<wmma::accumulator, 16, 16, 8, float> c[2][2];
    #pragma unroll
    for (int i = 0; i < 2; i++)
        #pragma unroll
        for (int j = 0; j < 2; j++) wmma::fill_fragment(c[i][j], 0.0f);

    int ar = t >> 1, ac = (t & 1) * 16;
    int br = t >> 3, bc = (t & 7) * 8;
    for (int k0 = 0; k0 < K; k0 += TCK) {
        if (k0) __syncthreads();
        #pragma unroll
        for (int m = 0; m < 4; m++) {
            float4 v = *(const float4*)(A + (size_t)(row0 + ar) * K + k0 + ac + m * 4);
            float* d = As + ar * LDA + ac + m * 4;
            d[0] = to_tf32(v.x); d[1] = to_tf32(v.y);
            d[2] = to_tf32(v.z); d[3] = to_tf32(v.w);
        }
        float sc = KSCALE ? kscale[k0 + br] : 1.0f;
        #pragma unroll
        for (int m = 0; m < 2; m++) {
            float4 v = *(const float4*)(B + (size_t)(k0 + br) * HF + col0 + bc + m * 4);
            float* d = Bs + br * LDB + bc + m * 4;
            d[0] = to_tf32(v.x * sc); d[1] = to_tf32(v.y * sc);
            d[2] = to_tf32(v.z * sc); d[3] = to_tf32(v.w * sc);
        }
        __syncthreads();
        #pragma unroll
        for (int kk = 0; kk < TCK; kk += 8) {
            wmma::fragment<wmma::matrix_a, 16, 16, 8, wmma::precision::tf32, wmma::row_major> a[2];
            wmma::fragment<wmma::matrix_b, 16, 16, 8, wmma::precision::tf32, wmma::row_major> b[2];
            wmma::load_matrix_sync(a[0], As + (wm * 32 +  0) * LDA + kk, LDA);
            wmma::load_matrix_sync(a[1], As + (wm * 32 + 16) * LDA + kk, LDA);
            wmma::load_matrix_sync(b[0], Bs + kk * LDB + wn * 32 +  0, LDB);
            wmma::load_matrix_sync(b[1], Bs + kk * LDB + wn * 32 + 16, LDB);
            #pragma unroll
            for (int i = 0; i < 2; i++)
                #pragma unroll
                for (int j = 0; j < 2; j++)
                    wmma::mma_sync(c[i][j], a[i], b[j], c[i][j]);
        }
    }
    __syncthreads();
    #pragma unroll
    for (int i = 0; i < 2; i++)
        #pragma unroll
        for (int j = 0; j < 2; j++)
            wmma::store_matrix_sync(buf + (wm * 32 + i * 16) * TCN + wn * 32 + j * 16,
                                    c[i][j], TCN, wmma::mem_row_major);
    __syncthreads();
    #pragma unroll
    for (int i = 0; i < 32; i++) {
        int idx = t + i * 256;
        int r = idx >> 6, cc = idx & 63;
        float v = buf[idx] + bias[col0 + cc];
        if (RELU) v = fmaxf(v, 0.0f);
        Cb[(size_t)(row0 + r) * ldc + col0 + cc] = v;
    }
}

// ---------------- 9. single-pass batchnorm stats -> scale/offset ------------
__global__ void k_bn_stats(const float* __restrict__ H,
                           const float* __restrict__ gamma,
                           const float* __restrict__ beta,
                           float* __restrict__ scol, float* __restrict__ ccol) {
    int tx = threadIdx.x, ty = threadIdx.y;
    int c = blockIdx.x * 32 + tx;
    __shared__ float redS[8][32], redQ[8][32];
    float s = 0.f, q = 0.f;
    for (int r = ty; r < BS; r += 8) {
        float v = H[(size_t)r * HH + c];
        s += v; q += v * v;
    }
    redS[ty][tx] = s; redQ[ty][tx] = q; __syncthreads();
    if (ty == 0) {
        float ts = 0.f, tq = 0.f;
        #pragma unroll
        for (int y = 0; y < 8; y++) { ts += redS[y][tx]; tq += redQ[y][tx]; }
        float mu  = ts * (1.0f / BS);
        float var = tq * (1.0f / BS) - mu * mu;
        float sc  = gamma[c] * rsqrtf(var + 1e-5f);
        scol[c] = sc;
        ccol[c] = beta[c] - mu * sc;
    }
}

// ---------------- 9b. rank-1 BN bias rows: R_z = c1 @ W2_z ------------------
__global__ void k_Rrow(const float* __restrict__ wAC2, const float* __restrict__ wCA2) {
    int c = blockIdx.x * 256 + threadIdx.x;   // 0..511
    const float* W = (c < HF) ? wAC2 : wCA2;
    int cc = c & (HF - 1);
    float acc = 0.f;
    for (int k = 0; k < HH; k++) acc += g_c1[k] * W[(size_t)k * HF + cc];
    if (c < HF) g_R1[cc] = acc; else g_R2[cc] = acc;
}

// ---------------- 10. fused BN2 + readout + softmax + modality mix ----------
__global__ void k_final2(const float* __restrict__ w_ro,
                         const float* __restrict__ cmix,
                         float* __restrict__ out) {
    int node = blockIdx.x * 8 + (threadIdx.x >> 5);
    int lane = threadIdx.x & 31;
    float m  = fmaxf(fmaxf(cmix[0], cmix[1]), fmaxf(cmix[2], cmix[3]));
    float e0 = expf(cmix[0] - m), e1 = expf(cmix[1] - m);
    float e2 = expf(cmix[2] - m), e3 = expf(cmix[3] - m);
    float inv = 1.0f / (e0 + e1 + e2 + e3);
    float w0 = e0 * inv, w1 = e1 * inv, w2 = e2 * inv, w3 = e3 * inv;

    float a0 = 0, a1 = 0, a2 = 0, a3 = 0;
    for (int f = lane; f < HH; f += 32) {
        float hsum = w0 * g_h[(size_t)(0 * NBLK + node) * HH + f]
                   + w1 * g_h[(size_t)(1 * NBLK + node) * HH + f]
                   + w2 * g_h[(size_t)(2 * NBLK + node) * HH + f]
                   + w3 * g_h[(size_t)(3 * NBLK + node) * HH + f];
        float x = g_s2col[f] * hsum + g_c2[f];   // weights sum to 1
        a0 += x * w_ro[f * 4 + 0];
        a1 += x * w_ro[f * 4 + 1];
        a2 += x * w_ro[f * 4 + 2];
        a3 += x * w_ro[f * 4 + 3];
    }
    #pragma unroll
    for (int o = 16; o; o >>= 1) {
        a0 += __shfl_xor_sync(0xffffffffu, a0, o);
        a1 += __shfl_xor_sync(0xffffffffu, a1, o);
        a2 += __shfl_xor_sync(0xffffffffu, a2, o);
        a3 += __shfl_xor_sync(0xffffffffu, a3, o);
    }
    if (lane == 0) {
        out[node * 4 + 0] = a0; out[node * 4 + 1] = a1;
        out[node * 4 + 2] = a2; out[node * 4 + 3] = a3;
    }
}

// ---------------- launch -----------------------------------------------------
extern "C" void kernel_launch(void* const* d_in, const int* in_sizes, int n_in,
                              void* d_out, int out_size) {
    (void)in_sizes; (void)n_in; (void)out_size;
    const float* features = (const float*)d_in[0];
    const float* sparse   = (const float*)d_in[1];
    const float* cmix     = (const float*)d_in[2];
    const float* wAC1     = (const float*)d_in[3];
    const float* bAC1     = (const float*)d_in[4];
    const float* wCA1     = (const float*)d_in[5];
    const float* bCA1     = (const float*)d_in[6];
    const float* wAC2     = (const float*)d_in[7];
    const float* bAC2     = (const float*)d_in[8];
    const float* wCA2     = (const float*)d_in[9];
    const float* bCA2     = (const float*)d_in[10];
    const float* gamma1   = (const float*)d_in[11];
    const float* beta1    = (const float*)d_in[12];
    const float* gamma2   = (const float*)d_in[13];
    const float* beta2    = (const float*)d_in[14];
    const float* w_ro     = (const float*)d_in[15];
    float* out = (float*)d_out;

    float*    Z1  = nullptr; cudaGetSymbolAddress((void**)&Z1,  g_Z1);
    float*    Z2  = nullptr; cudaGetSymbolAddress((void**)&Z2,  g_Z2);
    float*    H   = nullptr; cudaGetSymbolAddress((void**)&H,   g_h);
    float*    A1  = nullptr; cudaGetSymbolAddress((void**)&A1,  g_a1);
    float*    S1  = nullptr; cudaGetSymbolAddress((void**)&S1,  g_s1);
    float*    A2  = nullptr; cudaGetSymbolAddress((void**)&A2,  g_a2);
    float*    S2  = nullptr; cudaGetSymbolAddress((void**)&S2,  g_s2);
    unsigned* MB  = nullptr; cudaGetSymbolAddress((void**)&MB,  g_maskbits);
    unsigned* MTB = nullptr; cudaGetSymbolAddress((void**)&MTB, g_maskTbits);
    float*    S1C = nullptr; cudaGetSymbolAddress((void**)&S1C, g_s1col);
    float*    C1  = nullptr; cudaGetSymbolAddress((void**)&C1,  g_c1);
    float*    S2C = nullptr; cudaGetSymbolAddress((void**)&S2C, g_s2col);
    float*    C2  = nullptr; cudaGetSymbolAddress((void**)&C2,  g_c2);
    float*    R1  = nullptr; cudaGetSymbolAddress((void**)&R1,  g_R1);
    float*    R2  = nullptr; cudaGetSymbolAddress((void**)&R2,  g_R2);

    k_rownorm<<<BS / 8, 256>>>(features);
    k_corr_ind<<<dim3(16, 8, 7), 256>>>(sparse);
    k_mask_rows<<<2048, 256>>>();
    k_bt_mask<<<dim3(128, 16), 256>>>();
    k_degrees<<<16, 256>>>();

    // layer 1: aggregate-first, then tf32 GEMM pair with bias+relu
    k_spmm_dual<<<dim3(BS / 8, 1, 2), 256>>>(MTB, MB, features,
                                             A1, A2, S1, S2, Z1, Z2);
    k_gemm2_tc<1, 0><<<dim3(HF / TCN, BS / TCM, 2), 256>>>(
        Z1, Z2, wAC1, wCA1, bAC1, bCA1, nullptr, H, H, NF, HH, HF);
    k_bn_stats<<<HH / 32, dim3(32, 8)>>>(H, gamma1, beta1, S1C, C1);
    k_Rrow<<<2, 256>>>(wAC2, wCA2);

    // layer 2: BN1 folded into GEMM (kscale=s1col, bias=R_z), then SpMM+bias+relu
    k_gemm2_tc<0, 1><<<dim3(HF / TCN, BS / TCM, 2), 256>>>(
        H, H, wAC2, wCA2, R1, R2, S1C, Z1, Z2, HH, HF, 0);
    k_spmm_br_dual<<<dim3(BS / 8, 2, 2), 256>>>(MTB, MB, Z1, Z2,
                                                A1, A2, S1, S2, bAC2, bCA2, H, H + HF);
    k_bn_stats<<<HH / 32, dim3(32, 8)>>>(H, gamma2, beta2, S2C, C2);

    k_final2<<<NBLK / 8, 256>>>(w_ro, cmix, out);
}